// round 12
// baseline (speedup 1.0000x reference)
#include <cuda_runtime.h>
#include <cuda_fp16.h>
#include <mma.h>
#include <cstdint>

using namespace nvcuda;

// Problem constants (shapes fixed by the dataset)
#define MAX_N 100000
#define MAX_NP 100032           // padded to 64-row tiles for gemm1
#define MAX_E 3200000
#define IN_DIM 256
#define HID 64
#define OUTD 10
#define OUTP 16                 // h3 row padded to 16 halves (32B sector)

// ---------------- scratch (device globals; no allocation allowed) ----------
__device__ int    g_is64;
__device__ int    g_wnot = 0;           // set (and stays set) iff any weight != 1.0f
__device__ float  g_dinv[MAX_N];        // weighted in-degree -> d^{-1/2} in place
__device__ int    g_count[MAX_N];       // unweighted in-degree (CSR histogram)
__device__ int    g_start[MAX_N];       // CSR offsets (by destination)
__device__ int    g_cursor[MAX_N];      // scatter cursors
__device__ int    g_bsums[128];         // scan block sums -> exclusive prefix
__device__ int    g_csr_row[MAX_E];     // CSR: source row per edge (4B)
__device__ float  g_wcsr[MAX_E];        // CSR: permuted edge weight (only if wnot)
__device__ __half g_xh[MAX_NP * IN_DIM];// fp16 input features (padded rows zeroed)
__device__ __half g_W1h[HID * IN_DIM];
__device__ __half g_W2h[HID * HID];
__device__ __half g_h1h[MAX_N * HID];   // GEMM outputs
__device__ __half g_h2h[MAX_N * HID];   // aggregation outputs
__device__ __half g_h3h[MAX_N * OUTP];  // layer-3 GEMM out, padded rows

// ---------------- x -> fp16 conversion (padded rows zeroed) -----------------
__global__ void convert_x(const float* __restrict__ x, int M) {
    int tid = blockIdx.x * blockDim.x + threadIdx.x;   // one float4 per thread
    if (tid >= MAX_NP * (IN_DIM / 4)) return;
    int row = tid >> 6;                  // IN_DIM/4 = 64
    int c4 = (tid & 63) * 4;
    uint2 st;
    if (row < M) {
        float4 v = *(const float4*)(x + (size_t)row * IN_DIM + c4);
        __half2 a = __floats2half2_rn(v.x, v.y);
        __half2 b = __floats2half2_rn(v.z, v.w);
        st.x = *(unsigned*)&a;
        st.y = *(unsigned*)&b;
    } else {
        st.x = 0u; st.y = 0u;
    }
    *(uint2*)(g_xh + (size_t)row * IN_DIM + c4) = st;
}

// ---------------- fused init: zero arrays, detect dtype/weights, convert W --
__global__ void fused_init(const unsigned int* __restrict__ w, const float* __restrict__ ew,
                           const float* __restrict__ W1, const float* __restrict__ W2,
                           int E, int n) {
    int i = blockIdx.x * blockDim.x + threadIdx.x;
    if (i < n) {
        g_dinv[i] = 0.0f;
        g_count[i] = 0;
    }
    long long tot = (long long)gridDim.x * blockDim.x;
    for (long long j = i; j < E; j += tot)
        if (ew[j] != 1.0f) g_wnot = 1;
    if (i < (HID * IN_DIM + HID * HID) / 4) {
        int q = i * 4;
        if (q < HID * IN_DIM) {
            float4 v = *(const float4*)(W1 + q);
            __half2 a = __floats2half2_rn(v.x, v.y);
            __half2 b = __floats2half2_rn(v.z, v.w);
            *(uint2*)(g_W1h + q) = make_uint2(*(unsigned*)&a, *(unsigned*)&b);
        } else {
            int q2 = q - HID * IN_DIM;
            float4 v = *(const float4*)(W2 + q2);
            __half2 a = __floats2half2_rn(v.x, v.y);
            __half2 b = __floats2half2_rn(v.z, v.w);
            *(uint2*)(g_W2h + q2) = make_uint2(*(unsigned*)&a, *(unsigned*)&b);
        }
    }
    if (blockIdx.x == 0) {
        __shared__ int nz;
        if (threadIdx.x == 0) nz = 0;
        __syncthreads();
        long long nwords = (long long)E * 2;
        for (long long j = 1 + 2 * (long long)threadIdx.x; j < nwords && j < 4096;
             j += 2 * (long long)blockDim.x)
            if (w[j] != 0u) nz = 1;
        __syncthreads();
        if (threadIdx.x == 0) g_is64 = (nz == 0) ? 1 : 0;
    }
}

// Histogram pass: in-degree count (+ weighted degree when weights aren't 1).
__global__ void convert_deg(const void* __restrict__ ei, const float* __restrict__ ew, int E) {
    int e = blockIdx.x * blockDim.x + threadIdx.x;
    if (e >= E) return;
    int c;
    if (g_is64) c = (int)((const long long*)ei)[E + e];
    else        c = ((const int*)ei)[E + e];
    atomicAdd(&g_count[c], 1);
    if (g_wnot) atomicAdd(&g_dinv[c], ew[e]);
}

// Block-local exclusive scan of g_count -> g_start + block totals; also d^{-1/2}.
__global__ void scan_dinv(int n) {
    __shared__ int warp_sums[32];
    int i = blockIdx.x * 1024 + threadIdx.x;
    int v = (i < n) ? g_count[i] : 0;
    if (i < n) {
        float d = g_wnot ? g_dinv[i] : (float)v;
        g_dinv[i] = (d > 0.0f) ? rsqrtf(fmaxf(d, 1e-12f)) : 0.0f;
    }
    int lane = threadIdx.x & 31, wid = threadIdx.x >> 5;
    int x = v;
#pragma unroll
    for (int o = 1; o < 32; o <<= 1) {
        int y = __shfl_up_sync(~0u, x, o);
        if (lane >= o) x += y;
    }
    if (lane == 31) warp_sums[wid] = x;
    __syncthreads();
    if (wid == 0) {
        int s = warp_sums[lane];
#pragma unroll
        for (int o = 1; o < 32; o <<= 1) {
            int y = __shfl_up_sync(~0u, s, o);
            if (lane >= o) s += y;
        }
        warp_sums[lane] = s;
    }
    __syncthreads();
    int base = (wid > 0) ? warp_sums[wid - 1] : 0;
    int incl = x + base;
    if (i < n) g_start[i] = incl - v;
    if (threadIdx.x == 1023) g_bsums[blockIdx.x] = incl;
}

// Single small block: exclusive-scan the <=128 block sums in place.
__global__ void scan_sums(int nb) {
    __shared__ int ws[4];
    int tid = threadIdx.x;          // 128 threads
    int lane = tid & 31, wid = tid >> 5;
    int v = (tid < nb) ? g_bsums[tid] : 0;
    int x = v;
#pragma unroll
    for (int o = 1; o < 32; o <<= 1) {
        int y = __shfl_up_sync(~0u, x, o);
        if (lane >= o) x += y;
    }
    if (lane == 31) ws[wid] = x;
    __syncthreads();
    if (tid == 0) {
        int run = 0;
#pragma unroll
        for (int k = 0; k < 4; k++) { int t = ws[k]; ws[k] = run; run += t; }
    }
    __syncthreads();
    if (tid < 128) g_bsums[tid] = ws[wid] + x - v;   // exclusive
}

// Full-grid: apply block-sum offsets, init cursors.
__global__ void apply_offsets(int n) {
    int i = blockIdx.x * blockDim.x + threadIdx.x;
    if (i >= n) return;
    int s = g_start[i] + g_bsums[i >> 10];
    g_start[i] = s;
    g_cursor[i] = s;
}

// Atomic-cursor scatter into compact CSR (re-reads edge index).
__global__ void scatter_csr(const void* __restrict__ ei, const float* __restrict__ ew, int E) {
    int e = blockIdx.x * blockDim.x + threadIdx.x;
    if (e >= E) return;
    int r, c;
    if (g_is64) {
        const long long* p = (const long long*)ei;
        r = (int)p[e];
        c = (int)p[E + e];
    } else {
        const int* p = (const int*)ei;
        r = p[e];
        c = p[E + e];
    }
    int p = atomicAdd(&g_cursor[c], 1);
    g_csr_row[p] = r;
    if (g_wnot) g_wcsr[p] = ew[e];
}

// ---- GEMM1 v3: direct-global fp16 wmma, barrier-free mainloop --------------
// C[M][64] = A[Mp][256] @ W[64][256]^T (unscaled fp16 out).
// Block: 128 thr / 4 warps; warp grid 2x2, each warp owns a 32x32 output tile.
__global__ void gemm1_direct(const __half* __restrict__ A, const __half* __restrict__ Wh,
                             __half* __restrict__ C, int M) {
    __shared__ float cs[64 * 64];
    int warp = threadIdx.x >> 5;         // 0..3
    int m0 = blockIdx.x * 64;
    int mw = m0 + (warp >> 1) * 32;      // warp's first row (padded A: always valid)
    int nw = (warp & 1) * 32;            // warp's first col
    wmma::fragment<wmma::accumulator, 16, 16, 16, float> acc[2][2];
#pragma unroll
    for (int i = 0; i < 2; i++)
#pragma unroll
        for (int j = 0; j < 2; j++) wmma::fill_fragment(acc[i][j], 0.0f);
    wmma::fragment<wmma::matrix_a, 16, 16, 16, __half, wmma::row_major> fa[2];
    wmma::fragment<wmma::matrix_b, 16, 16, 16, __half, wmma::col_major> fb[2];
    const __half* a0 = A + (size_t)mw * IN_DIM;
    const __half* a1 = A + (size_t)(mw + 16) * IN_DIM;
    const __half* w0 = Wh + (size_t)nw * IN_DIM;
    const __half* w1 = Wh + (size_t)(nw + 16) * IN_DIM;
#pragma unroll
    for (int k = 0; k < IN_DIM; k += 16) {
        wmma::load_matrix_sync(fa[0], a0 + k, IN_DIM);
        wmma::load_matrix_sync(fa[1], a1 + k, IN_DIM);
        wmma::load_matrix_sync(fb[0], w0 + k, IN_DIM);
        wmma::load_matrix_sync(fb[1], w1 + k, IN_DIM);
#pragma unroll
        for (int i = 0; i < 2; i++)
#pragma unroll
            for (int j = 0; j < 2; j++)
                wmma::mma_sync(acc[i][j], fa[i], fb[j], acc[i][j]);
    }
    // epilogue via smem (coalesced fp16 stores, guarded)
    int mbase = (warp >> 1) * 32;
#pragma unroll
    for (int i = 0; i < 2; i++)
#pragma unroll
        for (int j = 0; j < 2; j++)
            wmma::store_matrix_sync(cs + (mbase + i * 16) * 64 + nw + j * 16,
                                    acc[i][j], 64, wmma::mem_row_major);
    __syncthreads();
    for (int i = threadIdx.x; i < 64 * 32; i += 128) {
        int r = i >> 5, p = i & 31;
        int row = m0 + r;
        if (row < M) {
            float2 v = *(float2*)&cs[r * 64 + p * 2];
            *(__half2*)(C + (size_t)row * 64 + p * 2) = __floats2half2_rn(v.x, v.y);
        }
    }
}

// In-place scale: h[row][*] *= dinv[row]  (64 halves per row)
__global__ void scale_h1(__half2* __restrict__ H, int M) {
    int i = blockIdx.x * blockDim.x + threadIdx.x;   // one half2 per thread
    if (i >= M * 32) return;
    int row = i >> 5;
    float dv = g_dinv[row];
    float2 v = __half22float2(H[i]);
    H[i] = __floats2half2_rn(v.x * dv, v.y * dv);
}

// ---- wmma GEMM, fp16 A; out = dinv[row]*(A[M][64] @ W[64][64]^T) -----------
__global__ void gemm_wmma_h(const __half* __restrict__ A, const __half* __restrict__ Wh,
                            __half* __restrict__ C, int M) {
    const int K = HID;
    __shared__ float cs[64 * 64];
    int warp = threadIdx.x >> 5;
    int m0 = blockIdx.x * 64;
    wmma::fragment<wmma::accumulator, 16, 16, 16, float> acc[4];
#pragma unroll
    for (int n = 0; n < 4; n++) wmma::fill_fragment(acc[n], 0.0f);
    wmma::fragment<wmma::matrix_a, 16, 16, 16, __half, wmma::row_major> fa;
    wmma::fragment<wmma::matrix_b, 16, 16, 16, __half, wmma::col_major> fb;
    int mrow = m0 + warp * 16;
    if (mrow + 16 <= M) {
        const __half* arow = A + (size_t)mrow * K;
#pragma unroll
        for (int k = 0; k < K; k += 16) {
            wmma::load_matrix_sync(fa, arow + k, K);
#pragma unroll
            for (int n = 0; n < 4; n++) {
                wmma::load_matrix_sync(fb, Wh + (size_t)n * 16 * K + k, K);
                wmma::mma_sync(acc[n], fa, fb, acc[n]);
            }
        }
    } else if (mrow < M) {
        __half* hs = (__half*)cs;
        for (int i = threadIdx.x & 31; i < 16 * K / 2; i += 32) {
            int r = i / (K / 2), q = (i % (K / 2)) * 2;
            unsigned v = 0u;
            if (mrow + r < M) v = *(const unsigned*)(A + (size_t)(mrow + r) * K + q);
            *(unsigned*)&hs[warp * 16 * K + r * K + q] = v;
        }
        __syncwarp();
#pragma unroll
        for (int k = 0; k < K; k += 16) {
            wmma::load_matrix_sync(fa, hs + warp * 16 * K + k, K);
#pragma unroll
            for (int n = 0; n < 4; n++) {
                wmma::load_matrix_sync(fb, Wh + (size_t)n * 16 * K + k, K);
                wmma::mma_sync(acc[n], fa, fb, acc[n]);
            }
        }
    }
    __syncthreads();
#pragma unroll
    for (int n = 0; n < 4; n++)
        wmma::store_matrix_sync(cs + warp * 16 * 64 + n * 16, acc[n], 64, wmma::mem_row_major);
    __syncthreads();
    for (int i = threadIdx.x; i < 64 * 32; i += 128) {
        int r = i >> 5, p = i & 31;
        int row = m0 + r;
        if (row < M) {
            float dv = g_dinv[row];
            float2 v = *(float2*)&cs[r * 64 + p * 2];
            *(__half2*)(C + (size_t)row * 64 + p * 2) = __floats2half2_rn(v.x * dv, v.y * dv);
        }
    }
}

// C[M][16pad] = dinv[row]*(A[M][64] @ W[10][64]^T); smem-staged A for coalescing.
__global__ void gemm_k64_n10(const __half* __restrict__ A, const float* __restrict__ W,
                             __half* __restrict__ C, int M) {
    __shared__ __half As[128 * 66];
    __shared__ float Ws[OUTD * 64];
    int tid = threadIdx.x;            // 128 threads
    for (int i = tid; i < OUTD * 64; i += 128) Ws[i] = W[i];
    int r0 = blockIdx.x * 128;
    for (int i = tid; i < 128 * 32; i += 128) {
        int r = i >> 5, q = (i & 31);
        unsigned v = 0u;
        if (r0 + r < M) v = *(const unsigned*)(A + (size_t)(r0 + r) * 64 + q * 2);
        *(unsigned*)&As[r * 66 + q * 2] = v;
    }
    __syncthreads();
    int row = r0 + tid;
    if (row >= M) return;
    float acc[OUTD] = {};
#pragma unroll
    for (int kq = 0; kq < 32; kq++) {
        float2 v = __half22float2(*(__half2*)&As[tid * 66 + kq * 2]);
#pragma unroll
        for (int o = 0; o < OUTD; o++)
            acc[o] += v.x * Ws[o * 64 + kq * 2 + 0] + v.y * Ws[o * 64 + kq * 2 + 1];
    }
    float dv = g_dinv[row];
    __half2 st[OUTP / 2];
#pragma unroll
    for (int o = 0; o < OUTD / 2; o++)
        st[o] = __floats2half2_rn(acc[2 * o] * dv, acc[2 * o + 1] * dv);
#pragma unroll
    for (int o = OUTD / 2; o < OUTP / 2; o++) st[o] = __floats2half2_rn(0.f, 0.f);
    *(uint4*)(C + (size_t)row * OUTP) = *(uint4*)&st[0];
    *(uint2*)(C + (size_t)row * OUTP + 8) = *(uint2*)&st[4];
}

// ---------------- CSR gather SpMM, D=64: out[c] = dinv[c]*sum h'[r] + b -----
template <int RELU>
__global__ void spmm_gather64h(const __half2* __restrict__ H, const float* __restrict__ b,
                               __half2* __restrict__ out, int N, int E) {
    int warp = (int)((blockIdx.x * (long long)blockDim.x + threadIdx.x) >> 5);
    int lane = threadIdx.x & 31;
    if (warp >= N) return;
    int s = g_start[warp];
    int e = (warp == N - 1) ? E : g_start[warp + 1];
    float2 acc = make_float2(0.0f, 0.0f);
    int j = s;
    if (!g_wnot) {
        for (; j + 3 < e; j += 4) {
            int r0 = g_csr_row[j], r1 = g_csr_row[j + 1];
            int r2 = g_csr_row[j + 2], r3 = g_csr_row[j + 3];
            float2 v0 = __half22float2(H[(size_t)r0 * 32 + lane]);
            float2 v1 = __half22float2(H[(size_t)r1 * 32 + lane]);
            float2 v2 = __half22float2(H[(size_t)r2 * 32 + lane]);
            float2 v3 = __half22float2(H[(size_t)r3 * 32 + lane]);
            acc.x += (v0.x + v1.x) + (v2.x + v3.x);
            acc.y += (v0.y + v1.y) + (v2.y + v3.y);
        }
        for (; j < e; j++) {
            float2 v0 = __half22float2(H[(size_t)g_csr_row[j] * 32 + lane]);
            acc.x += v0.x;
            acc.y += v0.y;
        }
    } else {
        for (; j < e; j++) {
            float w = g_wcsr[j];
            float2 v0 = __half22float2(H[(size_t)g_csr_row[j] * 32 + lane]);
            acc.x += w * v0.x;
            acc.y += w * v0.y;
        }
    }
    float dc = g_dinv[warp];
    float2 bb = *(const float2*)(b + lane * 2);
    acc.x = acc.x * dc + bb.x;
    acc.y = acc.y * dc + bb.y;
    if (RELU) { acc.x = fmaxf(acc.x, 0.0f); acc.y = fmaxf(acc.y, 0.0f); }
    out[(size_t)warp * 32 + lane] = __floats2half2_rn(acc.x, acc.y);
}

// CSR gather SpMM, padded D=16 fp16 payload -> fp32 out[10] + bias.
__global__ void spmm_gather10(const __half2* __restrict__ H, const float* __restrict__ b,
                              float* __restrict__ out, int N, int E) {
    int warp = (int)((blockIdx.x * (long long)blockDim.x + threadIdx.x) >> 5);
    int lane = threadIdx.x & 31;
    if (warp >= N) return;
    int s = g_start[warp];
    int e = (warp == N - 1) ? E : g_start[warp + 1];
    int l8 = lane & 7;
    float2 acc = make_float2(0.0f, 0.0f);
    if (lane < 8) {
        int j = s;
        if (!g_wnot) {
            for (; j + 1 < e; j += 2) {
                int r0 = g_csr_row[j], r1 = g_csr_row[j + 1];
                float2 v0 = __half22float2(H[(size_t)r0 * 8 + l8]);
                float2 v1 = __half22float2(H[(size_t)r1 * 8 + l8]);
                acc.x += v0.x + v1.x;
                acc.y += v0.y + v1.y;
            }
            for (; j < e; j++) {
                float2 v0 = __half22float2(H[(size_t)g_csr_row[j] * 8 + l8]);
                acc.x += v0.x;
                acc.y += v0.y;
            }
        } else {
            for (; j < e; j++) {
                float w = g_wcsr[j];
                float2 v0 = __half22float2(H[(size_t)g_csr_row[j] * 8 + l8]);
                acc.x += w * v0.x;
                acc.y += w * v0.y;
            }
        }
    }
    float dc = g_dinv[warp];
    if (lane < OUTD / 2) {
        float2 bb = *(const float2*)(b + lane * 2);
        float2 o = make_float2(acc.x * dc + bb.x, acc.y * dc + bb.y);
        *(float2*)(out + (size_t)warp * OUTD + lane * 2) = o;
    }
}

// ---------------- launch ---------------------------------------------------
static inline unsigned int cdiv(long long a, int b) { return (unsigned int)((a + b - 1) / b); }

extern "C" void kernel_launch(void* const* d_in, const int* in_sizes, int n_in,
                              void* d_out, int out_size) {
    const float* x  = (const float*)d_in[0];
    const void*  ei = d_in[1];
    const float* ew = (const float*)d_in[2];
    const float* W1 = (const float*)d_in[3];
    const float* b1 = (const float*)d_in[4];
    const float* W2 = (const float*)d_in[5];
    const float* b2 = (const float*)d_in[6];
    const float* W3 = (const float*)d_in[7];
    const float* b3 = (const float*)d_in[8];
    float* out = (float*)d_out;

    const int N = in_sizes[0] / IN_DIM;  // 100000
    const int E = in_sizes[1] / 2;       // 3200000
    (void)n_in; (void)out_size;

    __half *xh, *W1h, *W2h, *h1h, *h2h, *h3h;
    cudaGetSymbolAddress((void**)&xh, g_xh);
    cudaGetSymbolAddress((void**)&W1h, g_W1h);
    cudaGetSymbolAddress((void**)&W2h, g_W2h);
    cudaGetSymbolAddress((void**)&h1h, g_h1h);
    cudaGetSymbolAddress((void**)&h2h, g_h2h);
    cudaGetSymbolAddress((void**)&h3h, g_h3h);

    // side stream + fork/join events (one-time host setup)
    static cudaStream_t s2 = nullptr;
    static cudaEvent_t evFork0 = nullptr, evW = nullptr, evDinv = nullptr, evJoin = nullptr;
    if (s2 == nullptr) {
        cudaStreamCreateWithFlags(&s2, cudaStreamNonBlocking);
        cudaEventCreateWithFlags(&evFork0, cudaEventDisableTiming);
        cudaEventCreateWithFlags(&evW, cudaEventDisableTiming);
        cudaEventCreateWithFlags(&evDinv, cudaEventDisableTiming);
        cudaEventCreateWithFlags(&evJoin, cudaEventDisableTiming);
    }

    const int nb_scan = (N + 1023) / 1024;

    // --- fork convert_x immediately (needs only x) --------------------------
    cudaEventRecord(evFork0, 0);
    cudaStreamWaitEvent(s2, evFork0, 0);
    convert_x<<<cdiv((long long)MAX_NP * 64, 256), 256, 0, s2>>>(x, N);

    // --- main: init (W->fp16, zeros, flags) ---------------------------------
    fused_init<<<cdiv(N, 256), 256>>>((const unsigned int*)ei, ew, W1, W2, E, N);
    cudaEventRecord(evW, 0);

    // s2: gemm1 (needs xh + W1h), unscaled output
    cudaStreamWaitEvent(s2, evW, 0);
    gemm1_direct<<<MAX_NP / 64, 128, 0, s2>>>(xh, W1h, h1h, N);

    convert_deg<<<cdiv(E, 256), 256>>>(ei, ew, E);
    scan_dinv<<<nb_scan, 1024>>>(N);
    cudaEventRecord(evDinv, 0);

    // s2: after gemm1 AND dinv ready, scale h1 in place (overlaps scatter)
    cudaStreamWaitEvent(s2, evDinv, 0);
    scale_h1<<<cdiv((long long)N * 32, 256), 256, 0, s2>>>((__half2*)h1h, N);
    cudaEventRecord(evJoin, s2);

    scan_sums<<<1, 128>>>(nb_scan);
    apply_offsets<<<cdiv(N, 256), 256>>>(N);
    scatter_csr<<<cdiv(E, 256), 256>>>(ei, ew, E);
    cudaStreamWaitEvent(0, evJoin, 0);   // join before spmm1

    // --- layer 1: h2 = relu(dinv_c*(sum dinv_r*(x@W1^T)) + b1) --------------
    spmm_gather64h<1><<<cdiv((long long)N * 32, 256), 256>>>(
        (const __half2*)h1h, b1, (__half2*)h2h, N, E);

    // --- layer 2 ------------------------------------------------------------
    gemm_wmma_h<<<cdiv(N, 64), 128>>>(h2h, W2h, h1h, N);
    spmm_gather64h<1><<<cdiv((long long)N * 32, 256), 256>>>(
        (const __half2*)h1h, b2, (__half2*)h2h, N, E);

    // --- layer 3 ------------------------------------------------------------
    gemm_k64_n10<<<cdiv(N, 128), 128>>>(h2h, W3, h3h, N);
    spmm_gather10<<<cdiv((long long)N * 32, 256), 256>>>(
        (const __half2*)h3h, b3, out, N, E);
}

// round 13
// speedup vs baseline: 1.0368x; 1.0368x over previous
#include <cuda_runtime.h>
#include <cuda_fp16.h>
#include <mma.h>
#include <cstdint>

using namespace nvcuda;

// Problem constants (shapes fixed by the dataset)
#define MAX_N 100000
#define MAX_E 3200000
#define IN_DIM 256
#define HID 64
#define OUTD 10
#define OUTP 16                 // h3 row padded to 16 halves (32B sector)

// ---------------- scratch (device globals; no allocation allowed) ----------
__device__ int    g_is64;
__device__ int    g_wnot = 0;           // set (and stays set) iff any weight != 1.0f
__device__ float  g_dinv[MAX_N];        // weighted in-degree -> d^{-1/2} in place
__device__ int    g_count[MAX_N];       // unweighted in-degree (CSR histogram)
__device__ int    g_start[MAX_N];       // CSR offsets (by destination)
__device__ int    g_cursor[MAX_N];      // scatter cursors
__device__ int    g_bsums[128];         // scan block sums -> exclusive prefix
__device__ int    g_csr_row[MAX_E];     // CSR: source row per edge (4B)
__device__ float  g_wcsr[MAX_E];        // CSR: permuted edge weight (only if wnot)
__device__ __half g_W1h[HID * IN_DIM];
__device__ __half g_W2h[HID * HID];
__device__ __half g_h1h[MAX_N * HID];   // GEMM outputs
__device__ __half g_h2h[MAX_N * HID];   // aggregation outputs
__device__ __half g_h3h[MAX_N * OUTP];  // layer-3 GEMM out, padded rows

// ---------------- tiny first kernel: W1/W2 -> fp16 --------------------------
__global__ void convert_w(const float* __restrict__ W1, const float* __restrict__ W2) {
    int i = blockIdx.x * blockDim.x + threadIdx.x;
    if (i >= (HID * IN_DIM + HID * HID) / 4) return;
    int q = i * 4;
    if (q < HID * IN_DIM) {
        float4 v = *(const float4*)(W1 + q);
        __half2 a = __floats2half2_rn(v.x, v.y);
        __half2 b = __floats2half2_rn(v.z, v.w);
        *(uint2*)(g_W1h + q) = make_uint2(*(unsigned*)&a, *(unsigned*)&b);
    } else {
        int q2 = q - HID * IN_DIM;
        float4 v = *(const float4*)(W2 + q2);
        __half2 a = __floats2half2_rn(v.x, v.y);
        __half2 b = __floats2half2_rn(v.z, v.w);
        *(uint2*)(g_W2h + q2) = make_uint2(*(unsigned*)&a, *(unsigned*)&b);
    }
}

// ---------------- fused init: zero arrays, detect dtype/weights -------------
__global__ void fused_init(const unsigned int* __restrict__ w, const float* __restrict__ ew,
                           int E, int n) {
    int i = blockIdx.x * blockDim.x + threadIdx.x;
    if (i < n) {
        g_dinv[i] = 0.0f;
        g_count[i] = 0;
    }
    long long tot = (long long)gridDim.x * blockDim.x;
    for (long long j = i; j < E; j += tot)
        if (ew[j] != 1.0f) g_wnot = 1;
    if (blockIdx.x == 0) {
        __shared__ int nz;
        if (threadIdx.x == 0) nz = 0;
        __syncthreads();
        long long nwords = (long long)E * 2;
        for (long long j = 1 + 2 * (long long)threadIdx.x; j < nwords && j < 4096;
             j += 2 * (long long)blockDim.x)
            if (w[j] != 0u) nz = 1;
        __syncthreads();
        if (threadIdx.x == 0) g_is64 = (nz == 0) ? 1 : 0;
    }
}

// Histogram pass: in-degree count (+ weighted degree when weights aren't 1).
__global__ void convert_deg(const void* __restrict__ ei, const float* __restrict__ ew, int E) {
    int e = blockIdx.x * blockDim.x + threadIdx.x;
    if (e >= E) return;
    int c;
    if (g_is64) c = (int)((const long long*)ei)[E + e];
    else        c = ((const int*)ei)[E + e];
    atomicAdd(&g_count[c], 1);
    if (g_wnot) atomicAdd(&g_dinv[c], ew[e]);
}

// Block-local exclusive scan of g_count -> g_start + block totals; also d^{-1/2}.
__global__ void scan_dinv(int n) {
    __shared__ int warp_sums[32];
    int i = blockIdx.x * 1024 + threadIdx.x;
    int v = (i < n) ? g_count[i] : 0;
    if (i < n) {
        float d = g_wnot ? g_dinv[i] : (float)v;
        g_dinv[i] = (d > 0.0f) ? rsqrtf(fmaxf(d, 1e-12f)) : 0.0f;
    }
    int lane = threadIdx.x & 31, wid = threadIdx.x >> 5;
    int x = v;
#pragma unroll
    for (int o = 1; o < 32; o <<= 1) {
        int y = __shfl_up_sync(~0u, x, o);
        if (lane >= o) x += y;
    }
    if (lane == 31) warp_sums[wid] = x;
    __syncthreads();
    if (wid == 0) {
        int s = warp_sums[lane];
#pragma unroll
        for (int o = 1; o < 32; o <<= 1) {
            int y = __shfl_up_sync(~0u, s, o);
            if (lane >= o) s += y;
        }
        warp_sums[lane] = s;
    }
    __syncthreads();
    int base = (wid > 0) ? warp_sums[wid - 1] : 0;
    int incl = x + base;
    if (i < n) g_start[i] = incl - v;
    if (threadIdx.x == 1023) g_bsums[blockIdx.x] = incl;
}

// Single small block: exclusive-scan the <=128 block sums in place.
__global__ void scan_sums(int nb) {
    __shared__ int ws[4];
    int tid = threadIdx.x;          // 128 threads
    int lane = tid & 31, wid = tid >> 5;
    int v = (tid < nb) ? g_bsums[tid] : 0;
    int x = v;
#pragma unroll
    for (int o = 1; o < 32; o <<= 1) {
        int y = __shfl_up_sync(~0u, x, o);
        if (lane >= o) x += y;
    }
    if (lane == 31) ws[wid] = x;
    __syncthreads();
    if (tid == 0) {
        int run = 0;
#pragma unroll
        for (int k = 0; k < 4; k++) { int t = ws[k]; ws[k] = run; run += t; }
    }
    __syncthreads();
    if (tid < 128) g_bsums[tid] = ws[wid] + x - v;   // exclusive
}

// Full-grid: apply block-sum offsets, init cursors.
__global__ void apply_offsets(int n) {
    int i = blockIdx.x * blockDim.x + threadIdx.x;
    if (i >= n) return;
    int s = g_start[i] + g_bsums[i >> 10];
    g_start[i] = s;
    g_cursor[i] = s;
}

// Atomic-cursor scatter into compact CSR (re-reads edge index).
__global__ void scatter_csr(const void* __restrict__ ei, const float* __restrict__ ew, int E) {
    int e = blockIdx.x * blockDim.x + threadIdx.x;
    if (e >= E) return;
    int r, c;
    if (g_is64) {
        const long long* p = (const long long*)ei;
        r = (int)p[e];
        c = (int)p[E + e];
    } else {
        const int* p = (const int*)ei;
        r = p[e];
        c = p[E + e];
    }
    int p = atomicAdd(&g_cursor[c], 1);
    g_csr_row[p] = r;
    if (g_wnot) g_wcsr[p] = ew[e];
}

// ---- wmma GEMM v1, fp32 A staged+converted in smem; UNSCALED fp16 out ------
template <int K>
__global__ void gemm_wmma_f32A(const float* __restrict__ A, const __half* __restrict__ Wh,
                               __half* __restrict__ C, int M) {
    __shared__ __half As[64][72];    // 64x64 fp16 chunk, padded ldm=72
    __shared__ float cs[64 * 64];
    int warp = threadIdx.x >> 5;
    int m0 = blockIdx.x * 64;
    wmma::fragment<wmma::accumulator, 16, 16, 16, float> acc[4];
#pragma unroll
    for (int n = 0; n < 4; n++) wmma::fill_fragment(acc[n], 0.0f);
    wmma::fragment<wmma::matrix_a, 16, 16, 16, __half, wmma::row_major> fa;
    wmma::fragment<wmma::matrix_b, 16, 16, 16, __half, wmma::col_major> fb;

    for (int k0 = 0; k0 < K; k0 += 64) {
        for (int i = threadIdx.x; i < 64 * 16; i += 128) {
            int r = i >> 4, q = (i & 15) * 4;
            int row = m0 + r;
            float4 v = make_float4(0.f, 0.f, 0.f, 0.f);
            if (row < M) v = *(const float4*)(A + (size_t)row * K + k0 + q);
            __half2 a = __floats2half2_rn(v.x, v.y);
            __half2 b = __floats2half2_rn(v.z, v.w);
            *(uint2*)&As[r][q] = make_uint2(*(unsigned*)&a, *(unsigned*)&b);
        }
        __syncthreads();
#pragma unroll
        for (int kk = 0; kk < 64; kk += 16) {
            wmma::load_matrix_sync(fa, &As[warp * 16][kk], 72);
#pragma unroll
            for (int n = 0; n < 4; n++) {
                wmma::load_matrix_sync(fb, Wh + (size_t)n * 16 * K + k0 + kk, K);
                wmma::mma_sync(acc[n], fa, fb, acc[n]);
            }
        }
        __syncthreads();
    }
#pragma unroll
    for (int n = 0; n < 4; n++)
        wmma::store_matrix_sync(cs + warp * 16 * 64 + n * 16, acc[n], 64, wmma::mem_row_major);
    __syncthreads();
    for (int i = threadIdx.x; i < 64 * 32; i += 128) {
        int r = i >> 5, p = i & 31;
        int row = m0 + r;
        if (row < M) {
            float2 v = *(float2*)&cs[r * 64 + p * 2];
            *(__half2*)(C + (size_t)row * 64 + p * 2) = __floats2half2_rn(v.x, v.y);
        }
    }
}

// In-place scale: h[row][*] *= dinv[row]  (64 halves per row)
__global__ void scale_h1(__half2* __restrict__ H, int M) {
    int i = blockIdx.x * blockDim.x + threadIdx.x;   // one half2 per thread
    if (i >= M * 32) return;
    int row = i >> 5;
    float dv = g_dinv[row];
    float2 v = __half22float2(H[i]);
    H[i] = __floats2half2_rn(v.x * dv, v.y * dv);
}

// ---- wmma GEMM, fp16 A; out = dinv[row]*(A[M][64] @ W[64][64]^T) -----------
__global__ void gemm_wmma_h(const __half* __restrict__ A, const __half* __restrict__ Wh,
                            __half* __restrict__ C, int M) {
    const int K = HID;
    __shared__ float cs[64 * 64];
    int warp = threadIdx.x >> 5;
    int m0 = blockIdx.x * 64;
    wmma::fragment<wmma::accumulator, 16, 16, 16, float> acc[4];
#pragma unroll
    for (int n = 0; n < 4; n++) wmma::fill_fragment(acc[n], 0.0f);
    wmma::fragment<wmma::matrix_a, 16, 16, 16, __half, wmma::row_major> fa;
    wmma::fragment<wmma::matrix_b, 16, 16, 16, __half, wmma::col_major> fb;
    int mrow = m0 + warp * 16;
    if (mrow + 16 <= M) {
        const __half* arow = A + (size_t)mrow * K;
#pragma unroll
        for (int k = 0; k < K; k += 16) {
            wmma::load_matrix_sync(fa, arow + k, K);
#pragma unroll
            for (int n = 0; n < 4; n++) {
                wmma::load_matrix_sync(fb, Wh + (size_t)n * 16 * K + k, K);
                wmma::mma_sync(acc[n], fa, fb, acc[n]);
            }
        }
    } else if (mrow < M) {
        __half* hs = (__half*)cs;
        for (int i = threadIdx.x & 31; i < 16 * K / 2; i += 32) {
            int r = i / (K / 2), q = (i % (K / 2)) * 2;
            unsigned v = 0u;
            if (mrow + r < M) v = *(const unsigned*)(A + (size_t)(mrow + r) * K + q);
            *(unsigned*)&hs[warp * 16 * K + r * K + q] = v;
        }
        __syncwarp();
#pragma unroll
        for (int k = 0; k < K; k += 16) {
            wmma::load_matrix_sync(fa, hs + warp * 16 * K + k, K);
#pragma unroll
            for (int n = 0; n < 4; n++) {
                wmma::load_matrix_sync(fb, Wh + (size_t)n * 16 * K + k, K);
                wmma::mma_sync(acc[n], fa, fb, acc[n]);
            }
        }
    }
    __syncthreads();
#pragma unroll
    for (int n = 0; n < 4; n++)
        wmma::store_matrix_sync(cs + warp * 16 * 64 + n * 16, acc[n], 64, wmma::mem_row_major);
    __syncthreads();
    for (int i = threadIdx.x; i < 64 * 32; i += 128) {
        int r = i >> 5, p = i & 31;
        int row = m0 + r;
        if (row < M) {
            float dv = g_dinv[row];
            float2 v = *(float2*)&cs[r * 64 + p * 2];
            *(__half2*)(C + (size_t)row * 64 + p * 2) = __floats2half2_rn(v.x * dv, v.y * dv);
        }
    }
}

// C[M][16pad] = dinv[row]*(A[M][64] @ W[10][64]^T); smem-staged A for coalescing.
__global__ void gemm_k64_n10(const __half* __restrict__ A, const float* __restrict__ W,
                             __half* __restrict__ C, int M) {
    __shared__ __half As[128 * 66];
    __shared__ float Ws[OUTD * 64];
    int tid = threadIdx.x;            // 128 threads
    for (int i = tid; i < OUTD * 64; i += 128) Ws[i] = W[i];
    int r0 = blockIdx.x * 128;
    for (int i = tid; i < 128 * 32; i += 128) {
        int r = i >> 5, q = (i & 31);
        unsigned v = 0u;
        if (r0 + r < M) v = *(const unsigned*)(A + (size_t)(r0 + r) * 64 + q * 2);
        *(unsigned*)&As[r * 66 + q * 2] = v;
    }
    __syncthreads();
    int row = r0 + tid;
    if (row >= M) return;
    float acc[OUTD] = {};
#pragma unroll
    for (int kq = 0; kq < 32; kq++) {
        float2 v = __half22float2(*(__half2*)&As[tid * 66 + kq * 2]);
#pragma unroll
        for (int o = 0; o < OUTD; o++)
            acc[o] += v.x * Ws[o * 64 + kq * 2 + 0] + v.y * Ws[o * 64 + kq * 2 + 1];
    }
    float dv = g_dinv[row];
    __half2 st[OUTP / 2];
#pragma unroll
    for (int o = 0; o < OUTD / 2; o++)
        st[o] = __floats2half2_rn(acc[2 * o] * dv, acc[2 * o + 1] * dv);
#pragma unroll
    for (int o = OUTD / 2; o < OUTP / 2; o++) st[o] = __floats2half2_rn(0.f, 0.f);
    *(uint4*)(C + (size_t)row * OUTP) = *(uint4*)&st[0];
    *(uint2*)(C + (size_t)row * OUTP + 8) = *(uint2*)&st[4];
}

// ---------------- CSR gather SpMM, D=64: out[c] = dinv[c]*sum h'[r] + b -----
template <int RELU>
__global__ void spmm_gather64h(const __half2* __restrict__ H, const float* __restrict__ b,
                               __half2* __restrict__ out, int N, int E) {
    int warp = (int)((blockIdx.x * (long long)blockDim.x + threadIdx.x) >> 5);
    int lane = threadIdx.x & 31;
    if (warp >= N) return;
    int s = g_start[warp];
    int e = (warp == N - 1) ? E : g_start[warp + 1];
    float2 acc = make_float2(0.0f, 0.0f);
    int j = s;
    if (!g_wnot) {
        for (; j + 3 < e; j += 4) {
            int r0 = g_csr_row[j], r1 = g_csr_row[j + 1];
            int r2 = g_csr_row[j + 2], r3 = g_csr_row[j + 3];
            float2 v0 = __half22float2(H[(size_t)r0 * 32 + lane]);
            float2 v1 = __half22float2(H[(size_t)r1 * 32 + lane]);
            float2 v2 = __half22float2(H[(size_t)r2 * 32 + lane]);
            float2 v3 = __half22float2(H[(size_t)r3 * 32 + lane]);
            acc.x += (v0.x + v1.x) + (v2.x + v3.x);
            acc.y += (v0.y + v1.y) + (v2.y + v3.y);
        }
        for (; j < e; j++) {
            float2 v0 = __half22float2(H[(size_t)g_csr_row[j] * 32 + lane]);
            acc.x += v0.x;
            acc.y += v0.y;
        }
    } else {
        for (; j < e; j++) {
            float w = g_wcsr[j];
            float2 v0 = __half22float2(H[(size_t)g_csr_row[j] * 32 + lane]);
            acc.x += w * v0.x;
            acc.y += w * v0.y;
        }
    }
    float dc = g_dinv[warp];
    float2 bb = *(const float2*)(b + lane * 2);
    acc.x = acc.x * dc + bb.x;
    acc.y = acc.y * dc + bb.y;
    if (RELU) { acc.x = fmaxf(acc.x, 0.0f); acc.y = fmaxf(acc.y, 0.0f); }
    out[(size_t)warp * 32 + lane] = __floats2half2_rn(acc.x, acc.y);
}

// CSR gather SpMM, padded D=16 fp16 payload -> fp32 out[10] + bias.
__global__ void spmm_gather10(const __half2* __restrict__ H, const float* __restrict__ b,
                              float* __restrict__ out, int N, int E) {
    int warp = (int)((blockIdx.x * (long long)blockDim.x + threadIdx.x) >> 5);
    int lane = threadIdx.x & 31;
    if (warp >= N) return;
    int s = g_start[warp];
    int e = (warp == N - 1) ? E : g_start[warp + 1];
    int l8 = lane & 7;
    float2 acc = make_float2(0.0f, 0.0f);
    if (lane < 8) {
        int j = s;
        if (!g_wnot) {
            for (; j + 1 < e; j += 2) {
                int r0 = g_csr_row[j], r1 = g_csr_row[j + 1];
                float2 v0 = __half22float2(H[(size_t)r0 * 8 + l8]);
                float2 v1 = __half22float2(H[(size_t)r1 * 8 + l8]);
                acc.x += v0.x + v1.x;
                acc.y += v0.y + v1.y;
            }
            for (; j < e; j++) {
                float2 v0 = __half22float2(H[(size_t)g_csr_row[j] * 8 + l8]);
                acc.x += v0.x;
                acc.y += v0.y;
            }
        } else {
            for (; j < e; j++) {
                float w = g_wcsr[j];
                float2 v0 = __half22float2(H[(size_t)g_csr_row[j] * 8 + l8]);
                acc.x += w * v0.x;
                acc.y += w * v0.y;
            }
        }
    }
    float dc = g_dinv[warp];
    if (lane < OUTD / 2) {
        float2 bb = *(const float2*)(b + lane * 2);
        float2 o = make_float2(acc.x * dc + bb.x, acc.y * dc + bb.y);
        *(float2*)(out + (size_t)warp * OUTD + lane * 2) = o;
    }
}

// ---------------- launch ---------------------------------------------------
static inline unsigned int cdiv(long long a, int b) { return (unsigned int)((a + b - 1) / b); }

extern "C" void kernel_launch(void* const* d_in, const int* in_sizes, int n_in,
                              void* d_out, int out_size) {
    const float* x  = (const float*)d_in[0];
    const void*  ei = d_in[1];
    const float* ew = (const float*)d_in[2];
    const float* W1 = (const float*)d_in[3];
    const float* b1 = (const float*)d_in[4];
    const float* W2 = (const float*)d_in[5];
    const float* b2 = (const float*)d_in[6];
    const float* W3 = (const float*)d_in[7];
    const float* b3 = (const float*)d_in[8];
    float* out = (float*)d_out;

    const int N = in_sizes[0] / IN_DIM;  // 100000
    const int E = in_sizes[1] / 2;       // 3200000
    (void)n_in; (void)out_size;

    __half *W1h, *W2h, *h1h, *h2h, *h3h;
    cudaGetSymbolAddress((void**)&W1h, g_W1h);
    cudaGetSymbolAddress((void**)&W2h, g_W2h);
    cudaGetSymbolAddress((void**)&h1h, g_h1h);
    cudaGetSymbolAddress((void**)&h2h, g_h2h);
    cudaGetSymbolAddress((void**)&h3h, g_h3h);

    // side stream + fork/join events (one-time host setup)
    static cudaStream_t s2 = nullptr;
    static cudaEvent_t evW = nullptr, evDinv = nullptr, evJoin = nullptr;
    if (s2 == nullptr) {
        cudaStreamCreateWithFlags(&s2, cudaStreamNonBlocking);
        cudaEventCreateWithFlags(&evW, cudaEventDisableTiming);
        cudaEventCreateWithFlags(&evDinv, cudaEventDisableTiming);
        cudaEventCreateWithFlags(&evJoin, cudaEventDisableTiming);
    }

    const int nb_scan = (N + 1023) / 1024;

    // --- tiny W conversion first, then fork unscaled gemm1 ASAP -------------
    convert_w<<<cdiv((HID * IN_DIM + HID * HID) / 4, 256), 256>>>(W1, W2);
    cudaEventRecord(evW, 0);
    cudaStreamWaitEvent(s2, evW, 0);
    gemm_wmma_f32A<IN_DIM><<<cdiv(N, 64), 128, 0, s2>>>(x, W1h, h1h, N);

    // --- main preprocessing chain -------------------------------------------
    fused_init<<<cdiv(N, 256), 256>>>((const unsigned int*)ei, ew, E, N);
    convert_deg<<<cdiv(E, 256), 256>>>(ei, ew, E);
    scan_dinv<<<nb_scan, 1024>>>(N);
    cudaEventRecord(evDinv, 0);

    // s2: after gemm1 AND dinv ready, scale h1 in place (overlaps scatter)
    cudaStreamWaitEvent(s2, evDinv, 0);
    scale_h1<<<cdiv((long long)N * 32, 256), 256, 0, s2>>>((__half2*)h1h, N);
    cudaEventRecord(evJoin, s2);

    scan_sums<<<1, 128>>>(nb_scan);
    apply_offsets<<<cdiv(N, 256), 256>>>(N);
    scatter_csr<<<cdiv(E, 256), 256>>>(ei, ew, E);
    cudaStreamWaitEvent(0, evJoin, 0);   // join before spmm1

    // --- layer 1: h2 = relu(dinv_c*(sum dinv_r*(x@W1^T)) + b1) --------------
    spmm_gather64h<1><<<cdiv((long long)N * 32, 256), 256>>>(
        (const __half2*)h1h, b1, (__half2*)h2h, N, E);

    // --- layer 2 ------------------------------------------------------------
    gemm_wmma_h<<<cdiv(N, 64), 128>>>(h2h, W2h, h1h, N);
    spmm_gather64h<1><<<cdiv((long long)N * 32, 256), 256>>>(
        (const __half2*)h1h, b2, (__half2*)h2h, N, E);

    // --- layer 3 ------------------------------------------------------------
    gemm_k64_n10<<<cdiv(N, 128), 128>>>(h2h, W3, h3h, N);
    spmm_gather10<<<cdiv((long long)N * 32, 256), 256>>>(
        (const __half2*)h3h, b3, out, N, E);
}

// round 14
// speedup vs baseline: 1.1334x; 1.0932x over previous
#include <cuda_runtime.h>
#include <cuda_fp16.h>
#include <mma.h>
#include <cstdint>

using namespace nvcuda;

// Problem constants (shapes fixed by the dataset)
#define MAX_N 100000
#define MAX_E 3200000
#define IN_DIM 256
#define HID 64
#define OUTD 10
#define OUTP 16                 // h3 row padded to 16 halves (32B sector)

// ---------------- scratch (device globals; no allocation allowed) ----------
__device__ int    g_is64;
__device__ int    g_wnot = 0;           // set (and stays set) iff any weight != 1.0f
__device__ float  g_dinv[MAX_N];        // weighted in-degree -> d^{-1/2} in place
__device__ int    g_count[MAX_N];       // unweighted in-degree (CSR histogram)
__device__ int    g_start[MAX_N];       // CSR offsets (by destination)
__device__ int    g_cursor[MAX_N];      // scatter cursors
__device__ int    g_bsums[128];         // scan block sums -> exclusive prefix
__device__ int    g_csr_row[MAX_E];     // CSR: source row per edge (4B)
__device__ float  g_wcsr[MAX_E];        // CSR: permuted edge weight (only if wnot)
__device__ __half g_W1h[HID * IN_DIM];
__device__ __half g_W2h[HID * HID];
__device__ __half g_h1h[MAX_N * HID];   // GEMM outputs
__device__ __half g_h2h[MAX_N * HID];   // aggregation outputs
__device__ __half g_h3h[MAX_N * OUTP];  // layer-3 GEMM out, padded rows

// L1-bypass half2 load (L2-resident random gather stream)
__device__ __forceinline__ float2 ldcg_h2f2(const __half2* p) {
    unsigned u;
    asm volatile("ld.global.cg.b32 %0, [%1];" : "=r"(u) : "l"(p));
    return __half22float2(*(__half2*)&u);
}

// ---------------- tiny first kernel: W1/W2 -> fp16 --------------------------
__global__ void convert_w(const float* __restrict__ W1, const float* __restrict__ W2) {
    int i = blockIdx.x * blockDim.x + threadIdx.x;
    if (i >= (HID * IN_DIM + HID * HID) / 4) return;
    int q = i * 4;
    if (q < HID * IN_DIM) {
        float4 v = *(const float4*)(W1 + q);
        __half2 a = __floats2half2_rn(v.x, v.y);
        __half2 b = __floats2half2_rn(v.z, v.w);
        *(uint2*)(g_W1h + q) = make_uint2(*(unsigned*)&a, *(unsigned*)&b);
    } else {
        int q2 = q - HID * IN_DIM;
        float4 v = *(const float4*)(W2 + q2);
        __half2 a = __floats2half2_rn(v.x, v.y);
        __half2 b = __floats2half2_rn(v.z, v.w);
        *(uint2*)(g_W2h + q2) = make_uint2(*(unsigned*)&a, *(unsigned*)&b);
    }
}

// ---------------- fused init: zero arrays, detect dtype/weights -------------
__global__ void fused_init(const unsigned int* __restrict__ w, const float* __restrict__ ew,
                           int E, int n) {
    int i = blockIdx.x * blockDim.x + threadIdx.x;
    if (i < n) {
        g_dinv[i] = 0.0f;
        g_count[i] = 0;
    }
    long long tot = (long long)gridDim.x * blockDim.x;
    for (long long j = i; j < E; j += tot)
        if (ew[j] != 1.0f) g_wnot = 1;
    if (blockIdx.x == 0) {
        __shared__ int nz;
        if (threadIdx.x == 0) nz = 0;
        __syncthreads();
        long long nwords = (long long)E * 2;
        for (long long j = 1 + 2 * (long long)threadIdx.x; j < nwords && j < 4096;
             j += 2 * (long long)blockDim.x)
            if (w[j] != 0u) nz = 1;
        __syncthreads();
        if (threadIdx.x == 0) g_is64 = (nz == 0) ? 1 : 0;
    }
}

// Histogram pass: in-degree count (+ weighted degree when weights aren't 1).
__global__ void convert_deg(const void* __restrict__ ei, const float* __restrict__ ew, int E) {
    int e = blockIdx.x * blockDim.x + threadIdx.x;
    if (e >= E) return;
    int c;
    if (g_is64) c = (int)((const long long*)ei)[E + e];
    else        c = ((const int*)ei)[E + e];
    atomicAdd(&g_count[c], 1);
    if (g_wnot) atomicAdd(&g_dinv[c], ew[e]);
}

// Block-local exclusive scan of g_count -> g_start + block totals; also d^{-1/2}.
__global__ void scan_dinv(int n) {
    __shared__ int warp_sums[32];
    int i = blockIdx.x * 1024 + threadIdx.x;
    int v = (i < n) ? g_count[i] : 0;
    if (i < n) {
        float d = g_wnot ? g_dinv[i] : (float)v;
        g_dinv[i] = (d > 0.0f) ? rsqrtf(fmaxf(d, 1e-12f)) : 0.0f;
    }
    int lane = threadIdx.x & 31, wid = threadIdx.x >> 5;
    int x = v;
#pragma unroll
    for (int o = 1; o < 32; o <<= 1) {
        int y = __shfl_up_sync(~0u, x, o);
        if (lane >= o) x += y;
    }
    if (lane == 31) warp_sums[wid] = x;
    __syncthreads();
    if (wid == 0) {
        int s = warp_sums[lane];
#pragma unroll
        for (int o = 1; o < 32; o <<= 1) {
            int y = __shfl_up_sync(~0u, s, o);
            if (lane >= o) s += y;
        }
        warp_sums[lane] = s;
    }
    __syncthreads();
    int base = (wid > 0) ? warp_sums[wid - 1] : 0;
    int incl = x + base;
    if (i < n) g_start[i] = incl - v;
    if (threadIdx.x == 1023) g_bsums[blockIdx.x] = incl;
}

// Single small block: exclusive-scan the <=128 block sums in place.
__global__ void scan_sums(int nb) {
    __shared__ int ws[4];
    int tid = threadIdx.x;          // 128 threads
    int lane = tid & 31, wid = tid >> 5;
    int v = (tid < nb) ? g_bsums[tid] : 0;
    int x = v;
#pragma unroll
    for (int o = 1; o < 32; o <<= 1) {
        int y = __shfl_up_sync(~0u, x, o);
        if (lane >= o) x += y;
    }
    if (lane == 31) ws[wid] = x;
    __syncthreads();
    if (tid == 0) {
        int run = 0;
#pragma unroll
        for (int k = 0; k < 4; k++) { int t = ws[k]; ws[k] = run; run += t; }
    }
    __syncthreads();
    if (tid < 128) g_bsums[tid] = ws[wid] + x - v;   // exclusive
}

// Full-grid: apply block-sum offsets, init cursors.
__global__ void apply_offsets(int n) {
    int i = blockIdx.x * blockDim.x + threadIdx.x;
    if (i >= n) return;
    int s = g_start[i] + g_bsums[i >> 10];
    g_start[i] = s;
    g_cursor[i] = s;
}

// Atomic-cursor scatter into compact CSR (re-reads edge index).
__global__ void scatter_csr(const void* __restrict__ ei, const float* __restrict__ ew, int E) {
    int e = blockIdx.x * blockDim.x + threadIdx.x;
    if (e >= E) return;
    int r, c;
    if (g_is64) {
        const long long* p = (const long long*)ei;
        r = (int)p[e];
        c = (int)p[E + e];
    } else {
        const int* p = (const int*)ei;
        r = p[e];
        c = p[E + e];
    }
    int p = atomicAdd(&g_cursor[c], 1);
    g_csr_row[p] = r;
    if (g_wnot) g_wcsr[p] = ew[e];
}

// ---- wmma GEMM v1, fp32 A staged+converted in smem; UNSCALED fp16 out ------
template <int K>
__global__ void gemm_wmma_f32A(const float* __restrict__ A, const __half* __restrict__ Wh,
                               __half* __restrict__ C, int M) {
    __shared__ __half As[64][72];    // 64x64 fp16 chunk, padded ldm=72
    __shared__ float cs[64 * 64];
    int warp = threadIdx.x >> 5;
    int m0 = blockIdx.x * 64;
    wmma::fragment<wmma::accumulator, 16, 16, 16, float> acc[4];
#pragma unroll
    for (int n = 0; n < 4; n++) wmma::fill_fragment(acc[n], 0.0f);
    wmma::fragment<wmma::matrix_a, 16, 16, 16, __half, wmma::row_major> fa;
    wmma::fragment<wmma::matrix_b, 16, 16, 16, __half, wmma::col_major> fb;

    for (int k0 = 0; k0 < K; k0 += 64) {
        for (int i = threadIdx.x; i < 64 * 16; i += 128) {
            int r = i >> 4, q = (i & 15) * 4;
            int row = m0 + r;
            float4 v = make_float4(0.f, 0.f, 0.f, 0.f);
            if (row < M) v = *(const float4*)(A + (size_t)row * K + k0 + q);
            __half2 a = __floats2half2_rn(v.x, v.y);
            __half2 b = __floats2half2_rn(v.z, v.w);
            *(uint2*)&As[r][q] = make_uint2(*(unsigned*)&a, *(unsigned*)&b);
        }
        __syncthreads();
#pragma unroll
        for (int kk = 0; kk < 64; kk += 16) {
            wmma::load_matrix_sync(fa, &As[warp * 16][kk], 72);
#pragma unroll
            for (int n = 0; n < 4; n++) {
                wmma::load_matrix_sync(fb, Wh + (size_t)n * 16 * K + k0 + kk, K);
                wmma::mma_sync(acc[n], fa, fb, acc[n]);
            }
        }
        __syncthreads();
    }
#pragma unroll
    for (int n = 0; n < 4; n++)
        wmma::store_matrix_sync(cs + warp * 16 * 64 + n * 16, acc[n], 64, wmma::mem_row_major);
    __syncthreads();
    for (int i = threadIdx.x; i < 64 * 32; i += 128) {
        int r = i >> 5, p = i & 31;
        int row = m0 + r;
        if (row < M) {
            float2 v = *(float2*)&cs[r * 64 + p * 2];
            *(__half2*)(C + (size_t)row * 64 + p * 2) = __floats2half2_rn(v.x, v.y);
        }
    }
}

// In-place scale: h[row][*] *= dinv[row]  (64 halves per row)
__global__ void scale_h1(__half2* __restrict__ H, int M) {
    int i = blockIdx.x * blockDim.x + threadIdx.x;   // one half2 per thread
    if (i >= M * 32) return;
    int row = i >> 5;
    float dv = g_dinv[row];
    float2 v = __half22float2(H[i]);
    H[i] = __floats2half2_rn(v.x * dv, v.y * dv);
}

// ---- wmma GEMM, fp16 A; out = dinv[row]*(A[M][64] @ W[64][64]^T) -----------
__global__ void gemm_wmma_h(const __half* __restrict__ A, const __half* __restrict__ Wh,
                            __half* __restrict__ C, int M) {
    const int K = HID;
    __shared__ float cs[64 * 64];
    int warp = threadIdx.x >> 5;
    int m0 = blockIdx.x * 64;
    wmma::fragment<wmma::accumulator, 16, 16, 16, float> acc[4];
#pragma unroll
    for (int n = 0; n < 4; n++) wmma::fill_fragment(acc[n], 0.0f);
    wmma::fragment<wmma::matrix_a, 16, 16, 16, __half, wmma::row_major> fa;
    wmma::fragment<wmma::matrix_b, 16, 16, 16, __half, wmma::col_major> fb;
    int mrow = m0 + warp * 16;
    if (mrow + 16 <= M) {
        const __half* arow = A + (size_t)mrow * K;
#pragma unroll
        for (int k = 0; k < K; k += 16) {
            wmma::load_matrix_sync(fa, arow + k, K);
#pragma unroll
            for (int n = 0; n < 4; n++) {
                wmma::load_matrix_sync(fb, Wh + (size_t)n * 16 * K + k, K);
                wmma::mma_sync(acc[n], fa, fb, acc[n]);
            }
        }
    } else if (mrow < M) {
        __half* hs = (__half*)cs;
        for (int i = threadIdx.x & 31; i < 16 * K / 2; i += 32) {
            int r = i / (K / 2), q = (i % (K / 2)) * 2;
            unsigned v = 0u;
            if (mrow + r < M) v = *(const unsigned*)(A + (size_t)(mrow + r) * K + q);
            *(unsigned*)&hs[warp * 16 * K + r * K + q] = v;
        }
        __syncwarp();
#pragma unroll
        for (int k = 0; k < K; k += 16) {
            wmma::load_matrix_sync(fa, hs + warp * 16 * K + k, K);
#pragma unroll
            for (int n = 0; n < 4; n++) {
                wmma::load_matrix_sync(fb, Wh + (size_t)n * 16 * K + k, K);
                wmma::mma_sync(acc[n], fa, fb, acc[n]);
            }
        }
    }
    __syncthreads();
#pragma unroll
    for (int n = 0; n < 4; n++)
        wmma::store_matrix_sync(cs + warp * 16 * 64 + n * 16, acc[n], 64, wmma::mem_row_major);
    __syncthreads();
    for (int i = threadIdx.x; i < 64 * 32; i += 128) {
        int r = i >> 5, p = i & 31;
        int row = m0 + r;
        if (row < M) {
            float dv = g_dinv[row];
            float2 v = *(float2*)&cs[r * 64 + p * 2];
            *(__half2*)(C + (size_t)row * 64 + p * 2) = __floats2half2_rn(v.x * dv, v.y * dv);
        }
    }
}

// C[M][16pad] = dinv[row]*(A[M][64] @ W[10][64]^T); smem-staged A for coalescing.
__global__ void gemm_k64_n10(const __half* __restrict__ A, const float* __restrict__ W,
                             __half* __restrict__ C, int M) {
    __shared__ __half As[128 * 66];
    __shared__ float Ws[OUTD * 64];
    int tid = threadIdx.x;            // 128 threads
    for (int i = tid; i < OUTD * 64; i += 128) Ws[i] = W[i];
    int r0 = blockIdx.x * 128;
    for (int i = tid; i < 128 * 32; i += 128) {
        int r = i >> 5, q = (i & 31);
        unsigned v = 0u;
        if (r0 + r < M) v = *(const unsigned*)(A + (size_t)(r0 + r) * 64 + q * 2);
        *(unsigned*)&As[r * 66 + q * 2] = v;
    }
    __syncthreads();
    int row = r0 + tid;
    if (row >= M) return;
    float acc[OUTD] = {};
#pragma unroll
    for (int kq = 0; kq < 32; kq++) {
        float2 v = __half22float2(*(__half2*)&As[tid * 66 + kq * 2]);
#pragma unroll
        for (int o = 0; o < OUTD; o++)
            acc[o] += v.x * Ws[o * 64 + kq * 2 + 0] + v.y * Ws[o * 64 + kq * 2 + 1];
    }
    float dv = g_dinv[row];
    __half2 st[OUTP / 2];
#pragma unroll
    for (int o = 0; o < OUTD / 2; o++)
        st[o] = __floats2half2_rn(acc[2 * o] * dv, acc[2 * o + 1] * dv);
#pragma unroll
    for (int o = OUTD / 2; o < OUTP / 2; o++) st[o] = __floats2half2_rn(0.f, 0.f);
    *(uint4*)(C + (size_t)row * OUTP) = *(uint4*)&st[0];
    *(uint2*)(C + (size_t)row * OUTP + 8) = *(uint2*)&st[4];
}

// ---------------- CSR gather SpMM, D=64: out[c] = dinv[c]*sum h'[r] + b -----
// Unroll 8 + L1-bypass gathers for deeper MLP on the L2-latency-bound stream.
template <int RELU>
__global__ void spmm_gather64h(const __half2* __restrict__ H, const float* __restrict__ b,
                               __half2* __restrict__ out, int N, int E) {
    int warp = (int)((blockIdx.x * (long long)blockDim.x + threadIdx.x) >> 5);
    int lane = threadIdx.x & 31;
    if (warp >= N) return;
    int s = g_start[warp];
    int e = (warp == N - 1) ? E : g_start[warp + 1];
    float2 acc = make_float2(0.0f, 0.0f);
    int j = s;
    if (!g_wnot) {
        for (; j + 7 < e; j += 8) {
            int r0 = g_csr_row[j + 0], r1 = g_csr_row[j + 1];
            int r2 = g_csr_row[j + 2], r3 = g_csr_row[j + 3];
            int r4 = g_csr_row[j + 4], r5 = g_csr_row[j + 5];
            int r6 = g_csr_row[j + 6], r7 = g_csr_row[j + 7];
            float2 v0 = ldcg_h2f2(H + (size_t)r0 * 32 + lane);
            float2 v1 = ldcg_h2f2(H + (size_t)r1 * 32 + lane);
            float2 v2 = ldcg_h2f2(H + (size_t)r2 * 32 + lane);
            float2 v3 = ldcg_h2f2(H + (size_t)r3 * 32 + lane);
            float2 v4 = ldcg_h2f2(H + (size_t)r4 * 32 + lane);
            float2 v5 = ldcg_h2f2(H + (size_t)r5 * 32 + lane);
            float2 v6 = ldcg_h2f2(H + (size_t)r6 * 32 + lane);
            float2 v7 = ldcg_h2f2(H + (size_t)r7 * 32 + lane);
            acc.x += ((v0.x + v1.x) + (v2.x + v3.x)) + ((v4.x + v5.x) + (v6.x + v7.x));
            acc.y += ((v0.y + v1.y) + (v2.y + v3.y)) + ((v4.y + v5.y) + (v6.y + v7.y));
        }
        for (; j + 3 < e; j += 4) {
            int r0 = g_csr_row[j + 0], r1 = g_csr_row[j + 1];
            int r2 = g_csr_row[j + 2], r3 = g_csr_row[j + 3];
            float2 v0 = ldcg_h2f2(H + (size_t)r0 * 32 + lane);
            float2 v1 = ldcg_h2f2(H + (size_t)r1 * 32 + lane);
            float2 v2 = ldcg_h2f2(H + (size_t)r2 * 32 + lane);
            float2 v3 = ldcg_h2f2(H + (size_t)r3 * 32 + lane);
            acc.x += (v0.x + v1.x) + (v2.x + v3.x);
            acc.y += (v0.y + v1.y) + (v2.y + v3.y);
        }
        for (; j < e; j++) {
            float2 v0 = ldcg_h2f2(H + (size_t)g_csr_row[j] * 32 + lane);
            acc.x += v0.x;
            acc.y += v0.y;
        }
    } else {
        for (; j < e; j++) {
            float w = g_wcsr[j];
            float2 v0 = ldcg_h2f2(H + (size_t)g_csr_row[j] * 32 + lane);
            acc.x += w * v0.x;
            acc.y += w * v0.y;
        }
    }
    float dc = g_dinv[warp];
    float2 bb = *(const float2*)(b + lane * 2);
    acc.x = acc.x * dc + bb.x;
    acc.y = acc.y * dc + bb.y;
    if (RELU) { acc.x = fmaxf(acc.x, 0.0f); acc.y = fmaxf(acc.y, 0.0f); }
    out[(size_t)warp * 32 + lane] = __floats2half2_rn(acc.x, acc.y);
}

// CSR gather SpMM, padded D=16 fp16 payload -> fp32 out[10] + bias.
__global__ void spmm_gather10(const __half2* __restrict__ H, const float* __restrict__ b,
                              float* __restrict__ out, int N, int E) {
    int warp = (int)((blockIdx.x * (long long)blockDim.x + threadIdx.x) >> 5);
    int lane = threadIdx.x & 31;
    if (warp >= N) return;
    int s = g_start[warp];
    int e = (warp == N - 1) ? E : g_start[warp + 1];
    int l8 = lane & 7;
    float2 acc = make_float2(0.0f, 0.0f);
    if (lane < 8) {
        int j = s;
        if (!g_wnot) {
            for (; j + 3 < e; j += 4) {
                int r0 = g_csr_row[j + 0], r1 = g_csr_row[j + 1];
                int r2 = g_csr_row[j + 2], r3 = g_csr_row[j + 3];
                float2 v0 = ldcg_h2f2(H + (size_t)r0 * 8 + l8);
                float2 v1 = ldcg_h2f2(H + (size_t)r1 * 8 + l8);
                float2 v2 = ldcg_h2f2(H + (size_t)r2 * 8 + l8);
                float2 v3 = ldcg_h2f2(H + (size_t)r3 * 8 + l8);
                acc.x += (v0.x + v1.x) + (v2.x + v3.x);
                acc.y += (v0.y + v1.y) + (v2.y + v3.y);
            }
            for (; j < e; j++) {
                float2 v0 = ldcg_h2f2(H + (size_t)g_csr_row[j] * 8 + l8);
                acc.x += v0.x;
                acc.y += v0.y;
            }
        } else {
            for (; j < e; j++) {
                float w = g_wcsr[j];
                float2 v0 = ldcg_h2f2(H + (size_t)g_csr_row[j] * 8 + l8);
                acc.x += w * v0.x;
                acc.y += w * v0.y;
            }
        }
    }
    float dc = g_dinv[warp];
    if (lane < OUTD / 2) {
        float2 bb = *(const float2*)(b + lane * 2);
        float2 o = make_float2(acc.x * dc + bb.x, acc.y * dc + bb.y);
        *(float2*)(out + (size_t)warp * OUTD + lane * 2) = o;
    }
}

// ---------------- launch ---------------------------------------------------
static inline unsigned int cdiv(long long a, int b) { return (unsigned int)((a + b - 1) / b); }

extern "C" void kernel_launch(void* const* d_in, const int* in_sizes, int n_in,
                              void* d_out, int out_size) {
    const float* x  = (const float*)d_in[0];
    const void*  ei = d_in[1];
    const float* ew = (const float*)d_in[2];
    const float* W1 = (const float*)d_in[3];
    const float* b1 = (const float*)d_in[4];
    const float* W2 = (const float*)d_in[5];
    const float* b2 = (const float*)d_in[6];
    const float* W3 = (const float*)d_in[7];
    const float* b3 = (const float*)d_in[8];
    float* out = (float*)d_out;

    const int N = in_sizes[0] / IN_DIM;  // 100000
    const int E = in_sizes[1] / 2;       // 3200000
    (void)n_in; (void)out_size;

    __half *W1h, *W2h, *h1h, *h2h, *h3h;
    cudaGetSymbolAddress((void**)&W1h, g_W1h);
    cudaGetSymbolAddress((void**)&W2h, g_W2h);
    cudaGetSymbolAddress((void**)&h1h, g_h1h);
    cudaGetSymbolAddress((void**)&h2h, g_h2h);
    cudaGetSymbolAddress((void**)&h3h, g_h3h);

    // side stream + fork/join events (one-time host setup)
    static cudaStream_t s2 = nullptr;
    static cudaEvent_t evW = nullptr, evDinv = nullptr, evJoin = nullptr;
    if (s2 == nullptr) {
        cudaStreamCreateWithFlags(&s2, cudaStreamNonBlocking);
        cudaEventCreateWithFlags(&evW, cudaEventDisableTiming);
        cudaEventCreateWithFlags(&evDinv, cudaEventDisableTiming);
        cudaEventCreateWithFlags(&evJoin, cudaEventDisableTiming);
    }

    const int nb_scan = (N + 1023) / 1024;

    // --- tiny W conversion first, then fork unscaled gemm1 ASAP -------------
    convert_w<<<cdiv((HID * IN_DIM + HID * HID) / 4, 256), 256>>>(W1, W2);
    cudaEventRecord(evW, 0);
    cudaStreamWaitEvent(s2, evW, 0);
    gemm_wmma_f32A<IN_DIM><<<cdiv(N, 64), 128, 0, s2>>>(x, W1h, h1h, N);

    // --- main preprocessing chain -------------------------------------------
    fused_init<<<cdiv(N, 256), 256>>>((const unsigned int*)ei, ew, E, N);
    convert_deg<<<cdiv(E, 256), 256>>>(ei, ew, E);
    scan_dinv<<<nb_scan, 1024>>>(N);
    cudaEventRecord(evDinv, 0);

    // s2: after gemm1 AND dinv ready, scale h1 in place (overlaps scatter)
    cudaStreamWaitEvent(s2, evDinv, 0);
    scale_h1<<<cdiv((long long)N * 32, 256), 256, 0, s2>>>((__half2*)h1h, N);
    cudaEventRecord(evJoin, s2);

    scan_sums<<<1, 128>>>(nb_scan);
    apply_offsets<<<cdiv(N, 256), 256>>>(N);
    scatter_csr<<<cdiv(E, 256), 256>>>(ei, ew, E);
    cudaStreamWaitEvent(0, evJoin, 0);   // join before spmm1

    // --- layer 1: h2 = relu(dinv_c*(sum dinv_r*(x@W1^T)) + b1) --------------
    spmm_gather64h<1><<<cdiv((long long)N * 32, 256), 256>>>(
        (const __half2*)h1h, b1, (__half2*)h2h, N, E);

    // --- layer 2 ------------------------------------------------------------
    gemm_wmma_h<<<cdiv(N, 64), 128>>>(h2h, W2h, h1h, N);
    spmm_gather64h<1><<<cdiv((long long)N * 32, 256), 256>>>(
        (const __half2*)h1h, b2, (__half2*)h2h, N, E);

    // --- layer 3 ------------------------------------------------------------
    gemm_k64_n10<<<cdiv(N, 128), 128>>>(h2h, W3, h3h, N);
    spmm_gather10<<<cdiv((long long)N * 32, 256), 256>>>(
        (const __half2*)h3h, b3, out, N, E);
}

// round 15
// speedup vs baseline: 1.2148x; 1.0719x over previous
#include <cuda_runtime.h>
#include <cuda_fp16.h>
#include <mma.h>
#include <cstdint>

using namespace nvcuda;

// Problem constants (shapes fixed by the dataset)
#define MAX_N 100000
#define MAX_E 3200000
#define IN_DIM 256
#define HID 64
#define OUTD 10
#define OUTP 16                 // h3 row padded to 16 halves (32B sector)

// ---------------- scratch (device globals; no allocation allowed) ----------
__device__ int    g_is64;
__device__ int    g_wnot = 0;           // set (and stays set) iff any weight != 1.0f
__device__ float  g_dinv[MAX_N];        // weighted in-degree -> d^{-1/2} in place
__device__ int    g_count[MAX_N];       // unweighted in-degree (CSR histogram)
__device__ int    g_start[MAX_N];       // CSR offsets (by destination)
__device__ int    g_cursor[MAX_N];      // scatter cursors
__device__ int    g_bsums[128];         // scan block sums -> exclusive prefix
__device__ int    g_csr_row[MAX_E];     // CSR: source row per edge (4B)
__device__ float  g_wcsr[MAX_E];        // CSR: permuted edge weight (only if wnot)
__device__ __half g_W1h[HID * IN_DIM];
__device__ __half g_W2h[HID * HID];
__device__ __half g_h1h[MAX_N * HID];   // GEMM outputs
__device__ __half g_h2h[MAX_N * HID];   // aggregation outputs
__device__ __half g_h3h[MAX_N * OUTP];  // layer-3 GEMM out, padded rows

// L1-bypass half2 load (L2-resident random gather stream)
__device__ __forceinline__ float2 ldcg_h2f2(const __half2* p) {
    unsigned u;
    asm volatile("ld.global.cg.b32 %0, [%1];" : "=r"(u) : "l"(p));
    return __half22float2(*(__half2*)&u);
}

// ---------------- tiny first kernel: W1/W2 -> fp16 --------------------------
__global__ void convert_w(const float* __restrict__ W1, const float* __restrict__ W2) {
    int i = blockIdx.x * blockDim.x + threadIdx.x;
    if (i >= (HID * IN_DIM + HID * HID) / 4) return;
    int q = i * 4;
    if (q < HID * IN_DIM) {
        float4 v = *(const float4*)(W1 + q);
        __half2 a = __floats2half2_rn(v.x, v.y);
        __half2 b = __floats2half2_rn(v.z, v.w);
        *(uint2*)(g_W1h + q) = make_uint2(*(unsigned*)&a, *(unsigned*)&b);
    } else {
        int q2 = q - HID * IN_DIM;
        float4 v = *(const float4*)(W2 + q2);
        __half2 a = __floats2half2_rn(v.x, v.y);
        __half2 b = __floats2half2_rn(v.z, v.w);
        *(uint2*)(g_W2h + q2) = make_uint2(*(unsigned*)&a, *(unsigned*)&b);
    }
}

// ---------------- fused init: zero arrays, detect dtype/weights -------------
__global__ void fused_init(const unsigned int* __restrict__ w, const float* __restrict__ ew,
                           int E, int n) {
    int i = blockIdx.x * blockDim.x + threadIdx.x;
    if (i < n) {
        g_dinv[i] = 0.0f;
        g_count[i] = 0;
    }
    // all-ones check, vectorized float4 pass
    long long tot = (long long)gridDim.x * blockDim.x;
    int e4 = E >> 2;
    const float4* ew4 = (const float4*)ew;
    int bad = 0;
    for (long long j = i; j < e4; j += tot) {
        float4 v = ew4[j];
        if (v.x != 1.0f || v.y != 1.0f || v.z != 1.0f || v.w != 1.0f) bad = 1;
    }
    if (i < (E & 3) && ew[e4 * 4 + i] != 1.0f) bad = 1;
    if (bad) g_wnot = 1;
    if (blockIdx.x == 0) {
        __shared__ int nz;
        if (threadIdx.x == 0) nz = 0;
        __syncthreads();
        long long nwords = (long long)E * 2;
        for (long long j = 1 + 2 * (long long)threadIdx.x; j < nwords && j < 4096;
             j += 2 * (long long)blockDim.x)
            if (w[j] != 0u) nz = 1;
        __syncthreads();
        if (threadIdx.x == 0) g_is64 = (nz == 0) ? 1 : 0;
    }
}

// Histogram pass: in-degree count (+ weighted degree when weights aren't 1).
__global__ void convert_deg(const void* __restrict__ ei, const float* __restrict__ ew, int E) {
    int e = blockIdx.x * blockDim.x + threadIdx.x;
    if (e >= E) return;
    int c;
    if (g_is64) c = (int)((const long long*)ei)[E + e];
    else        c = ((const int*)ei)[E + e];
    atomicAdd(&g_count[c], 1);
    if (g_wnot) atomicAdd(&g_dinv[c], ew[e]);
}

// Block-local exclusive scan of g_count -> g_start + block totals; also d^{-1/2}.
__global__ void scan_dinv(int n) {
    __shared__ int warp_sums[32];
    int i = blockIdx.x * 1024 + threadIdx.x;
    int v = (i < n) ? g_count[i] : 0;
    if (i < n) {
        float d = g_wnot ? g_dinv[i] : (float)v;
        g_dinv[i] = (d > 0.0f) ? rsqrtf(fmaxf(d, 1e-12f)) : 0.0f;
    }
    int lane = threadIdx.x & 31, wid = threadIdx.x >> 5;
    int x = v;
#pragma unroll
    for (int o = 1; o < 32; o <<= 1) {
        int y = __shfl_up_sync(~0u, x, o);
        if (lane >= o) x += y;
    }
    if (lane == 31) warp_sums[wid] = x;
    __syncthreads();
    if (wid == 0) {
        int s = warp_sums[lane];
#pragma unroll
        for (int o = 1; o < 32; o <<= 1) {
            int y = __shfl_up_sync(~0u, s, o);
            if (lane >= o) s += y;
        }
        warp_sums[lane] = s;
    }
    __syncthreads();
    int base = (wid > 0) ? warp_sums[wid - 1] : 0;
    int incl = x + base;
    if (i < n) g_start[i] = incl - v;
    if (threadIdx.x == 1023) g_bsums[blockIdx.x] = incl;
}

// Single small block: exclusive-scan the <=128 block sums in place.
__global__ void scan_sums(int nb) {
    __shared__ int ws[4];
    int tid = threadIdx.x;          // 128 threads
    int lane = tid & 31, wid = tid >> 5;
    int v = (tid < nb) ? g_bsums[tid] : 0;
    int x = v;
#pragma unroll
    for (int o = 1; o < 32; o <<= 1) {
        int y = __shfl_up_sync(~0u, x, o);
        if (lane >= o) x += y;
    }
    if (lane == 31) ws[wid] = x;
    __syncthreads();
    if (tid == 0) {
        int run = 0;
#pragma unroll
        for (int k = 0; k < 4; k++) { int t = ws[k]; ws[k] = run; run += t; }
    }
    __syncthreads();
    if (tid < 128) g_bsums[tid] = ws[wid] + x - v;   // exclusive
}

// Full-grid: apply block-sum offsets, init cursors.
__global__ void apply_offsets(int n) {
    int i = blockIdx.x * blockDim.x + threadIdx.x;
    if (i >= n) return;
    int s = g_start[i] + g_bsums[i >> 10];
    g_start[i] = s;
    g_cursor[i] = s;
}

// Atomic-cursor scatter into compact CSR (re-reads edge index).
__global__ void scatter_csr(const void* __restrict__ ei, const float* __restrict__ ew, int E) {
    int e = blockIdx.x * blockDim.x + threadIdx.x;
    if (e >= E) return;
    int r, c;
    if (g_is64) {
        const long long* p = (const long long*)ei;
        r = (int)p[e];
        c = (int)p[E + e];
    } else {
        const int* p = (const int*)ei;
        r = p[e];
        c = p[E + e];
    }
    int p = atomicAdd(&g_cursor[c], 1);
    g_csr_row[p] = r;
    if (g_wnot) g_wcsr[p] = ew[e];
}

// ---- wmma GEMM v1, fp32 A staged+converted in smem; UNSCALED fp16 out ------
template <int K>
__global__ void gemm_wmma_f32A(const float* __restrict__ A, const __half* __restrict__ Wh,
                               __half* __restrict__ C, int M) {
    __shared__ __half As[64][72];    // 64x64 fp16 chunk, padded ldm=72
    __shared__ float cs[64 * 64];
    int warp = threadIdx.x >> 5;
    int m0 = blockIdx.x * 64;
    wmma::fragment<wmma::accumulator, 16, 16, 16, float> acc[4];
#pragma unroll
    for (int n = 0; n < 4; n++) wmma::fill_fragment(acc[n], 0.0f);
    wmma::fragment<wmma::matrix_a, 16, 16, 16, __half, wmma::row_major> fa;
    wmma::fragment<wmma::matrix_b, 16, 16, 16, __half, wmma::col_major> fb;

    for (int k0 = 0; k0 < K; k0 += 64) {
        for (int i = threadIdx.x; i < 64 * 16; i += 128) {
            int r = i >> 4, q = (i & 15) * 4;
            int row = m0 + r;
            float4 v = make_float4(0.f, 0.f, 0.f, 0.f);
            if (row < M) v = *(const float4*)(A + (size_t)row * K + k0 + q);
            __half2 a = __floats2half2_rn(v.x, v.y);
            __half2 b = __floats2half2_rn(v.z, v.w);
            *(uint2*)&As[r][q] = make_uint2(*(unsigned*)&a, *(unsigned*)&b);
        }
        __syncthreads();
#pragma unroll
        for (int kk = 0; kk < 64; kk += 16) {
            wmma::load_matrix_sync(fa, &As[warp * 16][kk], 72);
#pragma unroll
            for (int n = 0; n < 4; n++) {
                wmma::load_matrix_sync(fb, Wh + (size_t)n * 16 * K + k0 + kk, K);
                wmma::mma_sync(acc[n], fa, fb, acc[n]);
            }
        }
        __syncthreads();
    }
#pragma unroll
    for (int n = 0; n < 4; n++)
        wmma::store_matrix_sync(cs + warp * 16 * 64 + n * 16, acc[n], 64, wmma::mem_row_major);
    __syncthreads();
    for (int i = threadIdx.x; i < 64 * 32; i += 128) {
        int r = i >> 5, p = i & 31;
        int row = m0 + r;
        if (row < M) {
            float2 v = *(float2*)&cs[r * 64 + p * 2];
            *(__half2*)(C + (size_t)row * 64 + p * 2) = __floats2half2_rn(v.x, v.y);
        }
    }
}

// In-place scale: h[row][*] *= dinv[row]  (64 halves per row)
__global__ void scale_h1(__half2* __restrict__ H, int M) {
    int i = blockIdx.x * blockDim.x + threadIdx.x;   // one half2 per thread
    if (i >= M * 32) return;
    int row = i >> 5;
    float dv = g_dinv[row];
    float2 v = __half22float2(H[i]);
    H[i] = __floats2half2_rn(v.x * dv, v.y * dv);
}

// ---- wmma GEMM, fp16 A; out = dinv[row]*(A[M][64] @ W[64][64]^T) -----------
__global__ void gemm_wmma_h(const __half* __restrict__ A, const __half* __restrict__ Wh,
                            __half* __restrict__ C, int M) {
    const int K = HID;
    __shared__ float cs[64 * 64];
    int warp = threadIdx.x >> 5;
    int m0 = blockIdx.x * 64;
    wmma::fragment<wmma::accumulator, 16, 16, 16, float> acc[4];
#pragma unroll
    for (int n = 0; n < 4; n++) wmma::fill_fragment(acc[n], 0.0f);
    wmma::fragment<wmma::matrix_a, 16, 16, 16, __half, wmma::row_major> fa;
    wmma::fragment<wmma::matrix_b, 16, 16, 16, __half, wmma::col_major> fb;
    int mrow = m0 + warp * 16;
    if (mrow + 16 <= M) {
        const __half* arow = A + (size_t)mrow * K;
#pragma unroll
        for (int k = 0; k < K; k += 16) {
            wmma::load_matrix_sync(fa, arow + k, K);
#pragma unroll
            for (int n = 0; n < 4; n++) {
                wmma::load_matrix_sync(fb, Wh + (size_t)n * 16 * K + k, K);
                wmma::mma_sync(acc[n], fa, fb, acc[n]);
            }
        }
    } else if (mrow < M) {
        __half* hs = (__half*)cs;
        for (int i = threadIdx.x & 31; i < 16 * K / 2; i += 32) {
            int r = i / (K / 2), q = (i % (K / 2)) * 2;
            unsigned v = 0u;
            if (mrow + r < M) v = *(const unsigned*)(A + (size_t)(mrow + r) * K + q);
            *(unsigned*)&hs[warp * 16 * K + r * K + q] = v;
        }
        __syncwarp();
#pragma unroll
        for (int k = 0; k < K; k += 16) {
            wmma::load_matrix_sync(fa, hs + warp * 16 * K + k, K);
#pragma unroll
            for (int n = 0; n < 4; n++) {
                wmma::load_matrix_sync(fb, Wh + (size_t)n * 16 * K + k, K);
                wmma::mma_sync(acc[n], fa, fb, acc[n]);
            }
        }
    }
    __syncthreads();
#pragma unroll
    for (int n = 0; n < 4; n++)
        wmma::store_matrix_sync(cs + warp * 16 * 64 + n * 16, acc[n], 64, wmma::mem_row_major);
    __syncthreads();
    for (int i = threadIdx.x; i < 64 * 32; i += 128) {
        int r = i >> 5, p = i & 31;
        int row = m0 + r;
        if (row < M) {
            float dv = g_dinv[row];
            float2 v = *(float2*)&cs[r * 64 + p * 2];
            *(__half2*)(C + (size_t)row * 64 + p * 2) = __floats2half2_rn(v.x * dv, v.y * dv);
        }
    }
}

// C[M][16pad] = dinv[row]*(A[M][64] @ W[10][64]^T); smem-staged A for coalescing.
__global__ void gemm_k64_n10(const __half* __restrict__ A, const float* __restrict__ W,
                             __half* __restrict__ C, int M) {
    __shared__ __half As[128 * 66];
    __shared__ float Ws[OUTD * 64];
    int tid = threadIdx.x;            // 128 threads
    for (int i = tid; i < OUTD * 64; i += 128) Ws[i] = W[i];
    int r0 = blockIdx.x * 128;
    for (int i = tid; i < 128 * 32; i += 128) {
        int r = i >> 5, q = (i & 31);
        unsigned v = 0u;
        if (r0 + r < M) v = *(const unsigned*)(A + (size_t)(r0 + r) * 64 + q * 2);
        *(unsigned*)&As[r * 66 + q * 2] = v;
    }
    __syncthreads();
    int row = r0 + tid;
    if (row >= M) return;
    float acc[OUTD] = {};
#pragma unroll
    for (int kq = 0; kq < 32; kq++) {
        float2 v = __half22float2(*(__half2*)&As[tid * 66 + kq * 2]);
#pragma unroll
        for (int o = 0; o < OUTD; o++)
            acc[o] += v.x * Ws[o * 64 + kq * 2 + 0] + v.y * Ws[o * 64 + kq * 2 + 1];
    }
    float dv = g_dinv[row];
    __half2 st[OUTP / 2];
#pragma unroll
    for (int o = 0; o < OUTD / 2; o++)
        st[o] = __floats2half2_rn(acc[2 * o] * dv, acc[2 * o + 1] * dv);
#pragma unroll
    for (int o = OUTD / 2; o < OUTP / 2; o++) st[o] = __floats2half2_rn(0.f, 0.f);
    *(uint4*)(C + (size_t)row * OUTP) = *(uint4*)&st[0];
    *(uint2*)(C + (size_t)row * OUTP + 8) = *(uint2*)&st[4];
}

// ---------------- CSR gather SpMM, D=64: out[c] = dinv[c]*sum h'[r] + b -----
// Unroll 8 + L1-bypass gathers for deeper MLP on the L2-latency-bound stream.
template <int RELU>
__global__ void spmm_gather64h(const __half2* __restrict__ H, const float* __restrict__ b,
                               __half2* __restrict__ out, int N, int E) {
    int warp = (int)((blockIdx.x * (long long)blockDim.x + threadIdx.x) >> 5);
    int lane = threadIdx.x & 31;
    if (warp >= N) return;
    int s = g_start[warp];
    int e = (warp == N - 1) ? E : g_start[warp + 1];
    float2 acc = make_float2(0.0f, 0.0f);
    int j = s;
    if (!g_wnot) {
        for (; j + 7 < e; j += 8) {
            int r0 = g_csr_row[j + 0], r1 = g_csr_row[j + 1];
            int r2 = g_csr_row[j + 2], r3 = g_csr_row[j + 3];
            int r4 = g_csr_row[j + 4], r5 = g_csr_row[j + 5];
            int r6 = g_csr_row[j + 6], r7 = g_csr_row[j + 7];
            float2 v0 = ldcg_h2f2(H + (size_t)r0 * 32 + lane);
            float2 v1 = ldcg_h2f2(H + (size_t)r1 * 32 + lane);
            float2 v2 = ldcg_h2f2(H + (size_t)r2 * 32 + lane);
            float2 v3 = ldcg_h2f2(H + (size_t)r3 * 32 + lane);
            float2 v4 = ldcg_h2f2(H + (size_t)r4 * 32 + lane);
            float2 v5 = ldcg_h2f2(H + (size_t)r5 * 32 + lane);
            float2 v6 = ldcg_h2f2(H + (size_t)r6 * 32 + lane);
            float2 v7 = ldcg_h2f2(H + (size_t)r7 * 32 + lane);
            acc.x += ((v0.x + v1.x) + (v2.x + v3.x)) + ((v4.x + v5.x) + (v6.x + v7.x));
            acc.y += ((v0.y + v1.y) + (v2.y + v3.y)) + ((v4.y + v5.y) + (v6.y + v7.y));
        }
        for (; j + 3 < e; j += 4) {
            int r0 = g_csr_row[j + 0], r1 = g_csr_row[j + 1];
            int r2 = g_csr_row[j + 2], r3 = g_csr_row[j + 3];
            float2 v0 = ldcg_h2f2(H + (size_t)r0 * 32 + lane);
            float2 v1 = ldcg_h2f2(H + (size_t)r1 * 32 + lane);
            float2 v2 = ldcg_h2f2(H + (size_t)r2 * 32 + lane);
            float2 v3 = ldcg_h2f2(H + (size_t)r3 * 32 + lane);
            acc.x += (v0.x + v1.x) + (v2.x + v3.x);
            acc.y += (v0.y + v1.y) + (v2.y + v3.y);
        }
        for (; j < e; j++) {
            float2 v0 = ldcg_h2f2(H + (size_t)g_csr_row[j] * 32 + lane);
            acc.x += v0.x;
            acc.y += v0.y;
        }
    } else {
        for (; j < e; j++) {
            float w = g_wcsr[j];
            float2 v0 = ldcg_h2f2(H + (size_t)g_csr_row[j] * 32 + lane);
            acc.x += w * v0.x;
            acc.y += w * v0.y;
        }
    }
    float dc = g_dinv[warp];
    float2 bb = *(const float2*)(b + lane * 2);
    acc.x = acc.x * dc + bb.x;
    acc.y = acc.y * dc + bb.y;
    if (RELU) { acc.x = fmaxf(acc.x, 0.0f); acc.y = fmaxf(acc.y, 0.0f); }
    out[(size_t)warp * 32 + lane] = __floats2half2_rn(acc.x, acc.y);
}

// CSR gather SpMM, padded D=16 fp16 payload -> fp32 out[10] + bias.
// 4 edges processed in parallel per warp (lane>>3 = edge slot, lane&7 = dim pair),
// then shfl reduction folds the 4 partial accumulators.
__global__ void spmm_gather10(const __half2* __restrict__ H, const float* __restrict__ b,
                              float* __restrict__ out, int N, int E) {
    int warp = (int)((blockIdx.x * (long long)blockDim.x + threadIdx.x) >> 5);
    int lane = threadIdx.x & 31;
    if (warp >= N) return;
    int s = g_start[warp];
    int e = (warp == N - 1) ? E : g_start[warp + 1];
    int slot = lane >> 3;      // 0..3: which edge in the group of 4
    int l8 = lane & 7;         // dim pair 0..7
    float2 acc = make_float2(0.0f, 0.0f);
    if (!g_wnot) {
        for (int j = s + slot; j < e; j += 4) {
            int r = g_csr_row[j];
            float2 v = ldcg_h2f2(H + (size_t)r * 8 + l8);
            acc.x += v.x;
            acc.y += v.y;
        }
    } else {
        for (int j = s + slot; j < e; j += 4) {
            float w = g_wcsr[j];
            int r = g_csr_row[j];
            float2 v = ldcg_h2f2(H + (size_t)r * 8 + l8);
            acc.x += w * v.x;
            acc.y += w * v.y;
        }
    }
    // fold the 4 edge slots (lanes with equal l8 differ by multiples of 8)
    acc.x += __shfl_xor_sync(~0u, acc.x, 8);
    acc.y += __shfl_xor_sync(~0u, acc.y, 8);
    acc.x += __shfl_xor_sync(~0u, acc.x, 16);
    acc.y += __shfl_xor_sync(~0u, acc.y, 16);
    float dc = g_dinv[warp];
    if (lane < OUTD / 2) {
        float2 bb = *(const float2*)(b + lane * 2);
        float2 o = make_float2(acc.x * dc + bb.x, acc.y * dc + bb.y);
        *(float2*)(out + (size_t)warp * OUTD + lane * 2) = o;
    }
}

// ---------------- launch ---------------------------------------------------
static inline unsigned int cdiv(long long a, int b) { return (unsigned int)((a + b - 1) / b); }

extern "C" void kernel_launch(void* const* d_in, const int* in_sizes, int n_in,
                              void* d_out, int out_size) {
    const float* x  = (const float*)d_in[0];
    const void*  ei = d_in[1];
    const float* ew = (const float*)d_in[2];
    const float* W1 = (const float*)d_in[3];
    const float* b1 = (const float*)d_in[4];
    const float* W2 = (const float*)d_in[5];
    const float* b2 = (const float*)d_in[6];
    const float* W3 = (const float*)d_in[7];
    const float* b3 = (const float*)d_in[8];
    float* out = (float*)d_out;

    const int N = in_sizes[0] / IN_DIM;  // 100000
    const int E = in_sizes[1] / 2;       // 3200000
    (void)n_in; (void)out_size;

    __half *W1h, *W2h, *h1h, *h2h, *h3h;
    cudaGetSymbolAddress((void**)&W1h, g_W1h);
    cudaGetSymbolAddress((void**)&W2h, g_W2h);
    cudaGetSymbolAddress((void**)&h1h, g_h1h);
    cudaGetSymbolAddress((void**)&h2h, g_h2h);
    cudaGetSymbolAddress((void**)&h3h, g_h3h);

    // side stream + fork/join events (one-time host setup)
    static cudaStream_t s2 = nullptr;
    static cudaEvent_t evW = nullptr, evDinv = nullptr, evJoin = nullptr;
    if (s2 == nullptr) {
        cudaStreamCreateWithFlags(&s2, cudaStreamNonBlocking);
        cudaEventCreateWithFlags(&evW, cudaEventDisableTiming);
        cudaEventCreateWithFlags(&evDinv, cudaEventDisableTiming);
        cudaEventCreateWithFlags(&evJoin, cudaEventDisableTiming);
    }

    const int nb_scan = (N + 1023) / 1024;

    // --- tiny W conversion first, then fork unscaled gemm1 ASAP -------------
    convert_w<<<cdiv((HID * IN_DIM + HID * HID) / 4, 256), 256>>>(W1, W2);
    cudaEventRecord(evW, 0);
    cudaStreamWaitEvent(s2, evW, 0);
    gemm_wmma_f32A<IN_DIM><<<cdiv(N, 64), 128, 0, s2>>>(x, W1h, h1h, N);

    // --- main preprocessing chain -------------------------------------------
    fused_init<<<cdiv(N, 256), 256>>>((const unsigned int*)ei, ew, E, N);
    convert_deg<<<cdiv(E, 256), 256>>>(ei, ew, E);
    scan_dinv<<<nb_scan, 1024>>>(N);
    cudaEventRecord(evDinv, 0);

    // s2: after gemm1 AND dinv ready, scale h1 in place (overlaps scatter)
    cudaStreamWaitEvent(s2, evDinv, 0);
    scale_h1<<<cdiv((long long)N * 32, 256), 256, 0, s2>>>((__half2*)h1h, N);
    cudaEventRecord(evJoin, s2);

    scan_sums<<<1, 128>>>(nb_scan);
    apply_offsets<<<cdiv(N, 256), 256>>>(N);
    scatter_csr<<<cdiv(E, 256), 256>>>(ei, ew, E);
    cudaStreamWaitEvent(0, evJoin, 0);   // join before spmm1

    // --- layer 1: h2 = relu(dinv_c*(sum dinv_r*(x@W1^T)) + b1) --------------
    spmm_gather64h<1><<<cdiv((long long)N * 32, 256), 256>>>(
        (const __half2*)h1h, b1, (__half2*)h2h, N, E);

    // --- layer 2 ------------------------------------------------------------
    gemm_wmma_h<<<cdiv(N, 64), 128>>>(h2h, W2h, h1h, N);
    spmm_gather64h<1><<<cdiv((long long)N * 32, 256), 256>>>(
        (const __half2*)h1h, b2, (__half2*)h2h, N, E);

    // --- layer 3 ------------------------------------------------------------
    gemm_k64_n10<<<cdiv(N, 128), 128>>>(h2h, W3, h3h, N);
    spmm_gather10<<<cdiv((long long)N * 32, 256), 256>>>(
        (const __half2*)h3h, b3, out, N, E);
}